// round 3
// baseline (speedup 1.0000x reference)
#include <cuda_runtime.h>
#include <math.h>

// RBFSolver: out[0,f,t] = sum_k w_k / (1 + 4pi^2 ex^2)
//            out[1,f,t] = -2pi sum_k w_k ex / (1 + 4pi^2 ex^2)
// ex = exp(log f + log t + y_k), y = linspace(-50,50,500), w_k = exp(-y_k^2)*dy.
//
// Optimizations:
//  * ex = exp(s)*exp(y_k): one exp per (f,t); 44-entry table for exp(y_k).
//  * Gaussian weights negligible outside |y|<=4.5 (k=227..270): K 500 -> 44.
//  * exF = 2pi*ex folds the final 2pi into the accumulation exactly.
//  * Packed f32x2 math (sm_103a) for the FMA pipe.
//  * K split across 2 adjacent lanes per (f,t) pair, combined via shfl_xor(1):
//    doubles warps/SM (latency hiding), halves STG count.

#define NY_K0   227
#define NY_PAIR 22      // 44 points, 22 packed pairs; 11 per lane-half
#define F_DIM   512
#define T_DIM   256

typedef unsigned long long u64;

#define MUL2(o,a,b)   asm("mul.rn.f32x2 %0, %1, %2;"     : "=l"(o) : "l"(a), "l"(b))
#define ADD2(o,a,b)   asm("add.rn.f32x2 %0, %1, %2;"     : "=l"(o) : "l"(a), "l"(b))
#define FMA2(o,a,b,c) asm("fma.rn.f32x2 %0, %1, %2, %3;" : "=l"(o) : "l"(a), "l"(b), "l"(c))
#define PACK2(o,lo,hi)   asm("mov.b64 %0, {%1, %2};" : "=l"(o) : "f"(lo), "f"(hi))
#define UNPACK2(lo,hi,i) asm("mov.b64 {%0, %1}, %2;" : "=f"(lo), "=f"(hi) : "l"(i))
#define RCPA(o,a)     asm("rcp.approx.ftz.f32 %0, %1;" : "=f"(o) : "f"(a))

__global__ __launch_bounds__(T_DIM, 7)
void rbf_solver_kernel(const float* __restrict__ f_vec,
                       const float* __restrict__ log_t_vec,
                       float* __restrict__ out)
{
    // tbl[i].x = packed (E_2i, E_2i+1), tbl[i].y = packed (w_2i, w_2i+1)
    __shared__ ulonglong2 tbl[NY_PAIR];

    const float dy = 100.0f / 499.0f;

    if (threadIdx.x < NY_PAIR) {
        int k = NY_K0 + 2 * (int)threadIdx.x;
        float y0 = fmaf((float)k, dy, -50.0f);
        float y1 = y0 + dy;
        u64 E2, w2;
        PACK2(E2, __expf(y0), __expf(y1));
        PACK2(w2, __expf(-y0 * y0) * dy, __expf(-y1 * y1) * dy);
        tbl[threadIdx.x] = make_ulonglong2(E2, w2);
    }
    __syncthreads();

    // Lane pair (2i, 2i+1) shares one (f,t); each handles 11 of 22 pairs.
    const int f    = blockIdx.x >> 1;                          // 0..511
    const int t    = ((blockIdx.x & 1) << 7) + (threadIdx.x >> 1); // 0..255
    const int half = threadIdx.x & 1;

    const float s   = __logf(f_vec[f]) + log_t_vec[t];
    const float esc = __expf(s) * 6.283185307179586f;   // 2pi * exp(s)

    u64 esc2, one2, re2, im2;
    PACK2(esc2, esc, esc);
    {
        float one = 1.0f, zero = 0.0f;
        PACK2(one2, one, one);
        PACK2(re2, zero, zero);
        PACK2(im2, zero, zero);
    }

    const int i0 = half * (NY_PAIR / 2);

    #pragma unroll
    for (int j = 0; j < NY_PAIR / 2; ++j) {
        ulonglong2 v = tbl[i0 + j];          // LDS.128, pre-packed
        u64 E2 = v.x, w2 = v.y;

        u64 exF2;  MUL2(exF2, esc2, E2);            // 2pi*ex (x2)
        u64 d2;    FMA2(d2, exF2, exF2, one2);      // 1 + (2pi ex)^2 (x2)

        float dlo, dhi;  UNPACK2(dlo, dhi, d2);
        float rlo, rhi;
        RCPA(rlo, dlo);                             // MUFU.RCP
        RCPA(rhi, dhi);                             // MUFU.RCP
        u64 r2;    PACK2(r2, rlo, rhi);

        u64 tw2;   MUL2(tw2, w2, r2);               // w / denom (x2)
        ADD2(re2, re2, tw2);
        FMA2(im2, tw2, exF2, im2);                  // accumulates -a_im
    }

    float re_lo, re_hi, im_lo, im_hi;
    UNPACK2(re_lo, re_hi, re2);
    UNPACK2(im_lo, im_hi, im2);
    float re_s = re_lo + re_hi;
    float im_s = im_lo + im_hi;

    // Combine the two k-halves across the lane pair.
    re_s += __shfl_xor_sync(0xffffffffu, re_s, 1);
    im_s += __shfl_xor_sync(0xffffffffu, im_s, 1);

    const int idx = f * T_DIM + t;
    if (half == 0)
        out[idx] = re_s;                          // a_re
    else
        out[F_DIM * T_DIM + idx] = -im_s;         // a_im
}

extern "C" void kernel_launch(void* const* d_in, const int* in_sizes, int n_in,
                              void* d_out, int out_size)
{
    const float* f_vec     = (const float*)d_in[0];   // (512,)
    const float* log_t_vec = (const float*)d_in[1];   // (256,)
    float* out             = (float*)d_out;           // (2, 512, 256)

    (void)in_sizes; (void)n_in; (void)out_size;

    rbf_solver_kernel<<<F_DIM * 2, T_DIM>>>(f_vec, log_t_vec, out);
}

// round 4
// speedup vs baseline: 1.0485x; 1.0485x over previous
#include <cuda_runtime.h>
#include <math.h>

// RBFSolver: out[0,f,t] = sum_k w_k / (1 + 4pi^2 ex^2)
//            out[1,f,t] = -2pi sum_k w_k ex / (1 + 4pi^2 ex^2)
// ex = exp(log f + log t + y_k), y = linspace(-50,50,500), w_k = exp(-y_k^2)*dy.
//
// Optimizations:
//  * exp(log f + log t) = f * exp(log t): no log at all.
//  * Gaussian weights negligible outside |y|<=4.5 (k=227..270): K 500 -> 44.
//  * exF = 2pi*ex folds the final 2pi into the accumulation exactly.
//  * (E_k, w_k) table is input-independent: computed on the HOST and passed
//    as a by-value kernel parameter -> constant bank -> LDCU (uniform pipe),
//    no shared memory, no table build, no __syncthreads, no LDS latency.
//  * Packed f32x2 math (sm_103a) on the FMA pipe.
//  * Batched reciprocal: 1 MUFU.RCP per packed pair (r=rcp(d0*d1), r0=r*d1,
//    r1=r*d0) instead of 2 -> halves MUFU pressure and RCP latency per iter.

#define NY_K0   227
#define NY_PAIR 22      // 44 points, 22 packed pairs
#define F_DIM   512
#define T_DIM   256

typedef unsigned long long u64;

#define MUL2(o,a,b)   asm("mul.rn.f32x2 %0, %1, %2;"     : "=l"(o) : "l"(a), "l"(b))
#define ADD2(o,a,b)   asm("add.rn.f32x2 %0, %1, %2;"     : "=l"(o) : "l"(a), "l"(b))
#define FMA2(o,a,b,c) asm("fma.rn.f32x2 %0, %1, %2, %3;" : "=l"(o) : "l"(a), "l"(b), "l"(c))
#define PACK2(o,lo,hi)   asm("mov.b64 %0, {%1, %2};" : "=l"(o) : "f"(lo), "f"(hi))
#define UNPACK2(lo,hi,i) asm("mov.b64 {%0, %1}, %2;" : "=f"(lo), "=f"(hi) : "l"(i))
#define RCPA(o,a)     asm("rcp.approx.ftz.f32 %0, %1;" : "=f"(o) : "f"(a))

struct QuadTbl {
    // p[i] = (E_2i, E_2i+1, w_2i, w_2i+1); .xy and .zw are aligned 64-bit pairs
    float4 p[NY_PAIR];
};

__global__ __launch_bounds__(T_DIM, 4)
void rbf_solver_kernel(const float* __restrict__ f_vec,
                       const float* __restrict__ log_t_vec,
                       float* __restrict__ out,
                       const QuadTbl tbl)
{
    const int f = blockIdx.x;     // 0..511
    const int t = threadIdx.x;    // 0..255

    // esc = 2pi * exp(log f + log t) = 2pi * f * exp(log t)
    const float esc = 6.283185307179586f * f_vec[f] * __expf(log_t_vec[t]);

    u64 esc2, one2, re2, im2;
    PACK2(esc2, esc, esc);
    {
        float one = 1.0f, zero = 0.0f;
        PACK2(one2, one, one);
        PACK2(re2, zero, zero);
        PACK2(im2, zero, zero);
    }

    #pragma unroll
    for (int i = 0; i < NY_PAIR; ++i) {
        float4 v = tbl.p[i];                 // LDCU from param constant bank
        u64 E2, w2;
        PACK2(E2, v.x, v.y);
        PACK2(w2, v.z, v.w);

        u64 exF2;  MUL2(exF2, esc2, E2);            // 2pi*ex (x2)
        u64 d2;    FMA2(d2, exF2, exF2, one2);      // 1 + (2pi ex)^2 (x2)

        // Batched reciprocal: one MUFU for the pair.
        float dlo, dhi;  UNPACK2(dlo, dhi, d2);
        float pr = dlo * dhi;                       // <= ~9e17, no overflow
        float rr; RCPA(rr, pr);                     // MUFU.RCP (x1)
        float rlo = rr * dhi;
        float rhi = rr * dlo;
        u64 r2;    PACK2(r2, rlo, rhi);

        u64 tw2;   MUL2(tw2, w2, r2);               // w / denom (x2)
        ADD2(re2, re2, tw2);
        FMA2(im2, tw2, exF2, im2);                  // accumulates -a_im
    }

    float re_lo, re_hi, im_lo, im_hi;
    UNPACK2(re_lo, re_hi, re2);
    UNPACK2(im_lo, im_hi, im2);

    const int idx = f * T_DIM + t;
    out[idx]                 = re_lo + re_hi;       // a_re
    out[F_DIM * T_DIM + idx] = -(im_lo + im_hi);    // a_im
}

extern "C" void kernel_launch(void* const* d_in, const int* in_sizes, int n_in,
                              void* d_out, int out_size)
{
    const float* f_vec     = (const float*)d_in[0];   // (512,)
    const float* log_t_vec = (const float*)d_in[1];   // (256,)
    float* out             = (float*)d_out;           // (2, 512, 256)

    (void)in_sizes; (void)n_in; (void)out_size;

    // Input-independent quadrature table, built on the host each call
    // (deterministic, graph-capturable: passed by value as a kernel param).
    QuadTbl tbl;
    const double dy = 100.0 / 499.0;
    for (int i = 0; i < NY_PAIR; ++i) {
        double y0 = -50.0 + (double)(NY_K0 + 2 * i) * dy;
        double y1 = y0 + dy;
        tbl.p[i] = make_float4((float)exp(y0), (float)exp(y1),
                               (float)(exp(-y0 * y0) * dy),
                               (float)(exp(-y1 * y1) * dy));
    }

    rbf_solver_kernel<<<F_DIM, T_DIM>>>(f_vec, log_t_vec, out, tbl);
}